// round 5
// baseline (speedup 1.0000x reference)
#include <cuda_runtime.h>

#define BB 1024
#define TT 512
#define IN_DIM 16
#define HH 64
#define G3 192
#define WSTR 132   // padded floats per gate row in duplicated-W shared layout (528B)

// Scratch (device globals — allocation-free per harness rules)
// g_gx layout: ull index ((t*512 + bp)*192 + g), value = (gx[2bp][g], gx[2bp+1][g]) packed
__device__ float g_gx[(size_t)TT * BB * G3];   // 384 MiB
// g_out layout: ull index ((t*512 + bp)*64 + j), value = (h[2bp][j], h[2bp+1][j]) packed
__device__ float g_out[(size_t)TT * BB * HH];  // 128 MiB

// ---- f32x2 packed helpers (Blackwell FFMA2 path) ----
__device__ __forceinline__ unsigned long long pk2(float lo, float hi) {
    unsigned long long r;
    asm("mov.b64 %0, {%1, %2};" : "=l"(r) : "f"(lo), "f"(hi));
    return r;
}
__device__ __forceinline__ void upk2(unsigned long long v, float& lo, float& hi) {
    asm("mov.b64 {%0, %1}, %2;" : "=f"(lo), "=f"(hi) : "l"(v));
}
__device__ __forceinline__ unsigned long long fma2(unsigned long long a,
                                                   unsigned long long b,
                                                   unsigned long long c) {
    unsigned long long d;
    asm("fma.rn.f32x2 %0, %1, %2, %3;" : "=l"(d) : "l"(a), "l"(b), "l"(c));
    return d;
}

__device__ __forceinline__ float fsigmoid(float x) {
    return __fdividef(1.0f, 1.0f + __expf(-x));
}
__device__ __forceinline__ float ftanhf(float x) {
    float e = __expf(2.0f * x);
    return 1.0f - __fdividef(2.0f, e + 1.0f);
}

// ---------------------------------------------------------------------------
// gx GEMM (f32x2): writes g_gx packed layout.
// Block: 64 rows (32 row-pairs) x 192 gates, 256 threads.
// Thread tile: 4 row-pairs x 6 gates (24 packed accumulators).
// LAYER0: input is x [b][t][16] floats; else input is g_out packed ull layout.
// ---------------------------------------------------------------------------
template <int K, int LAYER0>
__global__ void __launch_bounds__(256) gx_gemm(
    const float* __restrict__ in,
    const float* __restrict__ W,
    const float* __restrict__ bias)
{
    extern __shared__ float sm[];
    unsigned long long* wsh = (unsigned long long*)sm;  // [K][192] dup-packed
    unsigned long long* ish = wsh + (size_t)K * 192;    // [32 pairs][K] row-pair packed

    const int t   = blockIdx.y;
    const int bp0 = blockIdx.x * 32;
    const int tid = threadIdx.x;

    // W fill: g-major for conflict-free STS (LDG scattered but L2-resident)
    for (int e = tid; e < 192 * K; e += 256) {
        int g = e % 192, k = e / 192;
        float w = W[g * K + k];
        wsh[k * 192 + g] = pk2(w, w);
    }

    if (LAYER0) {
        for (int e = tid; e < 32 * K; e += 256) {
            int pr = e / K, k = e % K;
            float v0 = __ldg(in + ((size_t)(bp0 + pr) * 2)     * ((size_t)TT * IN_DIM) + (size_t)t * IN_DIM + k);
            float v1 = __ldg(in + ((size_t)(bp0 + pr) * 2 + 1) * ((size_t)TT * IN_DIM) + (size_t)t * IN_DIM + k);
            ish[pr * K + k] = pk2(v0, v1);
        }
    } else {
        const unsigned long long* inq = (const unsigned long long*)in;
        for (int e = tid; e < 32 * K; e += 256) {
            int pr = e >> 6, k = e & 63;   // K==64 here
            ish[pr * 64 + k] = __ldg(inq + ((size_t)t * 512 + bp0 + pr) * 64 + k);
        }
    }
    __syncthreads();

    const int lane = tid & 31;
    const int mg   = tid >> 5;
    const int g0   = lane * 6;
    const int pr0  = mg * 4;

    unsigned long long acc[4][6];
#pragma unroll
    for (int j = 0; j < 6; j++) {
        float b = __ldg(bias + g0 + j);
        unsigned long long b2 = pk2(b, b);
#pragma unroll
        for (int q = 0; q < 4; q++) acc[q][j] = b2;
    }

#pragma unroll 4
    for (int k = 0; k < K; ++k) {
        unsigned long long iv0 = ish[(pr0 + 0) * K + k];
        unsigned long long iv1 = ish[(pr0 + 1) * K + k];
        unsigned long long iv2 = ish[(pr0 + 2) * K + k];
        unsigned long long iv3 = ish[(pr0 + 3) * K + k];
        const ulonglong2* wp2 = (const ulonglong2*)(wsh + (size_t)k * 192 + g0);
        ulonglong2 w01 = wp2[0], w23 = wp2[1], w45 = wp2[2];
        unsigned long long wv[6] = {w01.x, w01.y, w23.x, w23.y, w45.x, w45.y};
#pragma unroll
        for (int j = 0; j < 6; j++) {
            acc[0][j] = fma2(wv[j], iv0, acc[0][j]);
            acc[1][j] = fma2(wv[j], iv1, acc[1][j]);
            acc[2][j] = fma2(wv[j], iv2, acc[2][j]);
            acc[3][j] = fma2(wv[j], iv3, acc[3][j]);
        }
    }

    unsigned long long* og = (unsigned long long*)g_gx;
#pragma unroll
    for (int q = 0; q < 4; q++) {
        unsigned long long* op = og + ((size_t)t * 512 + bp0 + pr0 + q) * 192 + g0;
        ((ulonglong2*)op)[0] = make_ulonglong2(acc[q][0], acc[q][1]);
        ((ulonglong2*)op)[1] = make_ulonglong2(acc[q][2], acc[q][3]);
        ((ulonglong2*)op)[2] = make_ulonglong2(acc[q][4], acc[q][5]);
    }
}

// ---------------------------------------------------------------------------
// Recurrent GRU layer (f32x2). 128 blocks x 256 threads.
// Block = 4 warp-pairs; pair p owns batch row-pair bp = blk*4+p (rows 2bp,2bp+1).
// Within a pair, thread i (0..63) owns gates 3i..3i+2 (dot phase) and
// h-index j=i (update phase). Sync: named barrier per pair only.
// Shared: wdup [192 gates][132 floats] dup-packed (99KB, conflict-free),
//         hp   [32 k2][4 pairs][16B] packed h, gsh [4 pairs][192] packed gh.
// ---------------------------------------------------------------------------
__global__ void __launch_bounds__(256, 1) gru_rec(
    const float* __restrict__ Whh, const float* __restrict__ bhh)
{
    extern __shared__ float sm[];
    float* wdup = sm;                                            // 25344 floats
    float* hp   = sm + 25344;                                    // 512 floats
    unsigned long long* gsh = (unsigned long long*)(sm + 25856); // 768 ull

    const int tid = threadIdx.x;
    const int p   = tid >> 6;       // warp-pair 0..3
    const int i   = tid & 63;       // index within pair
    const int g0  = i * 3;
    const int bp  = blockIdx.x * 4 + p;   // global row-pair

    // fill duplicated W: wdup[g][ (k>>1)*4 + (k&1)*2 ] = (w,w)
    for (int e = tid; e < G3 * HH; e += 256) {
        int g = e >> 6, k = e & 63;
        float w = Whh[e];
        *(unsigned long long*)(wdup + (size_t)g * WSTR + (k >> 1) * 4 + (k & 1) * 2) = pk2(w, w);
    }
    for (int e = tid; e < 512; e += 256) hp[e] = 0.0f;

    unsigned long long bb0, bb1, bb2;
    {
        float b0 = __ldg(bhh + g0), b1 = __ldg(bhh + g0 + 1), b2 = __ldg(bhh + g0 + 2);
        bb0 = pk2(b0, b0); bb1 = pk2(b1, b1); bb2 = pk2(b2, b2);
    }
    __syncthreads();

    const ulonglong2* wq0 = (const ulonglong2*)(wdup + (size_t)(g0 + 0) * WSTR);
    const ulonglong2* wq1 = (const ulonglong2*)(wdup + (size_t)(g0 + 1) * WSTR);
    const ulonglong2* wq2 = (const ulonglong2*)(wdup + (size_t)(g0 + 2) * WSTR);
    const ulonglong2* hq  = ((const ulonglong2*)hp) + p;   // entry k2*4

    const unsigned long long* gxp = (const unsigned long long*)g_gx;
    const size_t gxbase = (size_t)bp * G3 + i;
    unsigned long long* outp = (unsigned long long*)g_out + (size_t)bp * HH + i;
    unsigned long long* hwr =
        (unsigned long long*)((char*)hp + (size_t)((i >> 1) * 4 + p) * 16 + (i & 1) * 8);
    unsigned long long* gwr = gsh + p * G3 + g0;
    const unsigned long long* grd = gsh + p * G3 + i;

    float h0 = 0.0f, h1 = 0.0f;

    // prefetch gx for t=0
    unsigned long long px0 = __ldg(gxp + gxbase);
    unsigned long long px1 = __ldg(gxp + gxbase + 64);
    unsigned long long px2 = __ldg(gxp + gxbase + 128);

#pragma unroll 1
    for (int t = 0; t < TT; ++t) {
        unsigned long long cx0 = px0, cx1 = px1, cx2 = px2;
        size_t nb = gxbase + (size_t)((t + 1 < TT) ? t + 1 : t) * (512 * G3);
        px0 = __ldg(gxp + nb);
        px1 = __ldg(gxp + nb + 64);
        px2 = __ldg(gxp + nb + 128);

        // ---- dot phase: gh (packed rows) for gates 3i..3i+2 ----
        unsigned long long a0 = bb0, a1 = bb1, a2 = bb2;
#pragma unroll 8
        for (int k2 = 0; k2 < 32; ++k2) {
            ulonglong2 hv = hq[k2 * 4];
            ulonglong2 w0 = wq0[k2];
            ulonglong2 w1 = wq1[k2];
            ulonglong2 w2 = wq2[k2];
            a0 = fma2(w0.x, hv.x, a0); a0 = fma2(w0.y, hv.y, a0);
            a1 = fma2(w1.x, hv.x, a1); a1 = fma2(w1.y, hv.y, a1);
            a2 = fma2(w2.x, hv.x, a2); a2 = fma2(w2.y, hv.y, a2);
        }
        gwr[0] = a0; gwr[1] = a1; gwr[2] = a2;
        asm volatile("bar.sync %0, 64;" :: "r"(p + 1) : "memory");

        // ---- update phase: thread owns h[2bp][i], h[2bp+1][i] ----
        unsigned long long gr = grd[0];
        unsigned long long gz = grd[64];
        unsigned long long gn = grd[128];
        float xr0, xr1, xz0, xz1, xn0, xn1;
        float hr0, hr1, hz0, hz1, hn0, hn1;
        upk2(cx0, xr0, xr1); upk2(cx1, xz0, xz1); upk2(cx2, xn0, xn1);
        upk2(gr, hr0, hr1);  upk2(gz, hz0, hz1);  upk2(gn, hn0, hn1);

        float r0 = fsigmoid(xr0 + hr0), r1 = fsigmoid(xr1 + hr1);
        float z0 = fsigmoid(xz0 + hz0), z1 = fsigmoid(xz1 + hz1);
        float n0 = ftanhf(fmaf(r0, hn0, xn0));
        float n1 = ftanhf(fmaf(r1, hn1, xn1));
        h0 = fmaf(z0, h0 - n0, n0);
        h1 = fmaf(z1, h1 - n1, n1);

        unsigned long long hpk = pk2(h0, h1);
        *hwr = hpk;
        outp[(size_t)t * (512 * HH)] = hpk;
        asm volatile("bar.sync %0, 64;" :: "r"(p + 1) : "memory");
    }
}

// ---------------------------------------------------------------------------
// Head: y[b] = fc2_b + fc2_w . relu(fc1_w @ h_last[b] + fc1_b)
// h_last from g_out packed layout at t=TT-1.
// ---------------------------------------------------------------------------
__global__ void __launch_bounds__(256) head_kernel(
    const float* __restrict__ fc1w, const float* __restrict__ fc1b,
    const float* __restrict__ fc2w, const float* __restrict__ fc2b,
    float* __restrict__ y)
{
    __shared__ float s1[32 * 64];
    __shared__ float sb1[32];
    __shared__ float sw2[32];
    const int tid = threadIdx.x;
    for (int e = tid; e < 2048; e += 256) s1[e] = fc1w[e];
    if (tid < 32) { sb1[tid] = fc1b[tid]; sw2[tid] = fc2w[tid]; }
    __syncthreads();

    const int b = blockIdx.x * 256 + tid;
    const float* hpair = g_out + (((size_t)(TT - 1) * 512 + (b >> 1)) * 64) * 2;
    const int half = b & 1;
    float hv[64];
#pragma unroll
    for (int k = 0; k < 64; k++) hv[k] = __ldg(hpair + k * 2 + half);

    float acc = __ldg(fc2b);
#pragma unroll
    for (int j = 0; j < 32; j++) {
        float s = sb1[j];
#pragma unroll
        for (int k = 0; k < 64; k++) s = fmaf(s1[j * 64 + k], hv[k], s);
        acc = fmaf(sw2[j], fmaxf(s, 0.0f), acc);
    }
    y[b] = acc;
}

// ---------------------------------------------------------------------------
extern "C" void kernel_launch(void* const* d_in, const int* in_sizes, int n_in,
                              void* d_out, int out_size)
{
    const float* x    = (const float*)d_in[0];
    const float* Wih0 = (const float*)d_in[1];
    const float* Whh0 = (const float*)d_in[2];
    const float* bih0 = (const float*)d_in[3];
    const float* bhh0 = (const float*)d_in[4];
    const float* Wih1 = (const float*)d_in[5];
    const float* Whh1 = (const float*)d_in[6];
    const float* bih1 = (const float*)d_in[7];
    const float* bhh1 = (const float*)d_in[8];
    const float* Wih2 = (const float*)d_in[9];
    const float* Whh2 = (const float*)d_in[10];
    const float* bih2 = (const float*)d_in[11];
    const float* bhh2 = (const float*)d_in[12];
    const float* fc1w = (const float*)d_in[13];
    const float* fc1b = (const float*)d_in[14];
    const float* fc2w = (const float*)d_in[15];
    const float* fc2b = (const float*)d_in[16];
    float* y = (float*)d_out;
    (void)in_sizes; (void)n_in; (void)out_size;

    const int gemm64_smem = (64 * 192 + 32 * 64) * 8;        // 114688
    const int gemm16_smem = (16 * 192 + 32 * 16) * 8;        // 28672
    const int rec_smem    = 25344 * 4 + 512 * 4 + 768 * 8;   // 109568

    cudaFuncSetAttribute((const void*)gx_gemm<64, 0>,
                         cudaFuncAttributeMaxDynamicSharedMemorySize, gemm64_smem);
    cudaFuncSetAttribute((const void*)gru_rec,
                         cudaFuncAttributeMaxDynamicSharedMemorySize, rec_smem);

    float* outp = nullptr;
    cudaGetSymbolAddress((void**)&outp, g_out);

    const dim3 gg(16, 512);

    // layer 0
    gx_gemm<16, 1><<<gg, 256, gemm16_smem>>>(x, Wih0, bih0);
    gru_rec<<<128, 256, rec_smem>>>(Whh0, bhh0);
    // layer 1
    gx_gemm<64, 0><<<gg, 256, gemm64_smem>>>(outp, Wih1, bih1);
    gru_rec<<<128, 256, rec_smem>>>(Whh1, bhh1);
    // layer 2
    gx_gemm<64, 0><<<gg, 256, gemm64_smem>>>(outp, Wih2, bih2);
    gru_rec<<<128, 256, rec_smem>>>(Whh2, bhh2);
    // head
    head_kernel<<<4, 256>>>(fc1w, fc1b, fc2w, fc2b, y);
}

// round 6
// speedup vs baseline: 1.0759x; 1.0759x over previous
#include <cuda_runtime.h>

#define BB 1024
#define TT 512
#define G3  192
#define HHH 64

typedef unsigned long long ull;

// Scratch (device globals — allocation-free). Plain float layouts.
__device__ float g_gx[(size_t)TT * BB * G3];    // [t][b][192]
__device__ float g_out[(size_t)TT * BB * HHH];  // [t][b][64]

// ---- f32x2 packed helpers ----
__device__ __forceinline__ ull pk2(float lo, float hi) {
    ull r; asm("mov.b64 %0, {%1, %2};" : "=l"(r) : "f"(lo), "f"(hi)); return r;
}
__device__ __forceinline__ void upk2(ull v, float& lo, float& hi) {
    asm("mov.b64 {%0, %1}, %2;" : "=f"(lo), "=f"(hi) : "l"(v));
}
__device__ __forceinline__ ull fma2(ull a, ull b, ull c) {
    ull d; asm("fma.rn.f32x2 %0, %1, %2, %3;" : "=l"(d) : "l"(a), "l"(b), "l"(c)); return d;
}
__device__ __forceinline__ float hsum2(ull v) {
    float lo, hi; upk2(v, lo, hi); return lo + hi;
}

__device__ __forceinline__ float fsigmoid(float x) {
    return __fdividef(1.0f, 1.0f + __expf(-x));
}
__device__ __forceinline__ float ftanhf(float x) {
    float e = __expf(2.0f * x);
    return 1.0f - __fdividef(2.0f, e + 1.0f);
}

// ---------------------------------------------------------------------------
// gx GEMM, k-packed f32x2 (no duplication).
// Block: 64 rows x 192 gates, 256 threads, thread tile 8 rows x 6 gates.
// g_gx[t][b][g] = bias[g] + sum_k in[b][k] * W[g][k]
// ---------------------------------------------------------------------------
template <int K, int LAYER0>
__global__ void __launch_bounds__(256) gx_gemm(
    const float* __restrict__ in,
    const float* __restrict__ W,
    const float* __restrict__ bias)
{
    constexpr int K2 = K / 2;
    extern __shared__ float sm[];
    ull* wsh = (ull*)sm;                 // [K2][192]  k-packed W
    ull* ish = wsh + (size_t)K2 * 192;   // [64][K2+1] padded, k-packed inputs

    const int t   = blockIdx.y;
    const int b0  = blockIdx.x * 64;
    const int tid = threadIdx.x;

    for (int e = tid; e < 192 * K2; e += 256) {
        int g = e % 192, kp = e / 192;
        wsh[kp * 192 + g] = ((const ull*)W)[(size_t)g * K2 + kp];
    }
    if (LAYER0) {
        for (int e = tid; e < 64 * K2; e += 256) {
            int m = e / K2, kp = e % K2;
            ish[m * (K2 + 1) + kp] =
                ((const ull*)in)[((size_t)(b0 + m) * TT + t) * K2 + kp];
        }
    } else {
        for (int e = tid; e < 64 * K2; e += 256) {
            int m = e / K2, kp = e % K2;
            ish[m * (K2 + 1) + kp] =
                ((const ull*)in)[((size_t)t * BB + b0 + m) * K2 + kp];
        }
    }
    __syncthreads();

    const int lane = tid & 31;
    const int mg   = tid >> 5;
    const int g0   = lane * 6;
    const int m0   = mg * 8;

    ull acc[8][6];
#pragma unroll
    for (int q = 0; q < 8; q++)
#pragma unroll
        for (int j = 0; j < 6; j++) acc[q][j] = 0ULL;

#pragma unroll 4
    for (int kp = 0; kp < K2; ++kp) {
        ull iv[8];
#pragma unroll
        for (int q = 0; q < 8; q++) iv[q] = ish[(m0 + q) * (K2 + 1) + kp];
        const ulonglong2* wp = (const ulonglong2*)(wsh + (size_t)kp * 192 + g0);
        ulonglong2 w01 = wp[0], w23 = wp[1], w45 = wp[2];
        ull wv[6] = {w01.x, w01.y, w23.x, w23.y, w45.x, w45.y};
#pragma unroll
        for (int q = 0; q < 8; q++)
#pragma unroll
            for (int j = 0; j < 6; j++)
                acc[q][j] = fma2(wv[j], iv[q], acc[q][j]);
    }

    float bb[6];
#pragma unroll
    for (int j = 0; j < 6; j++) bb[j] = __ldg(bias + g0 + j);

#pragma unroll
    for (int q = 0; q < 8; q++) {
        float* op = g_gx + ((size_t)t * BB + b0 + m0 + q) * G3 + g0;
        float2 v;
        v.x = hsum2(acc[q][0]) + bb[0]; v.y = hsum2(acc[q][1]) + bb[1]; *(float2*)(op)     = v;
        v.x = hsum2(acc[q][2]) + bb[2]; v.y = hsum2(acc[q][3]) + bb[3]; *(float2*)(op + 2) = v;
        v.x = hsum2(acc[q][4]) + bb[4]; v.y = hsum2(acc[q][5]) + bb[5]; *(float2*)(op + 4) = v;
    }
}

// ---------------------------------------------------------------------------
// Recurrent GRU layer. 128 blocks x 256 threads; block owns 8 batch rows.
// Dot phase: thread (triple tau = tid&63, slice s = tid>>6) holds W for gates
// 3tau..3tau+2, k in [16s,16s+16), IN REGISTERS (24 f32x2), accumulates all
// 8 rows -> partials to shared. Update phase: warp w owns row w; lane j owns
// h[j], h[j+32]; sums the 4 k-slice partials, applies gates, writes h + g_out.
// ---------------------------------------------------------------------------
__global__ void __launch_bounds__(256, 1) gru_rec(
    const float* __restrict__ Whh, const float* __restrict__ bhh)
{
    __shared__ float hsh[8 * 64];        // h state, [row][64]
    __shared__ float psh[4 * 8 * G3];    // partials, [slice][row][gate]

    const int tid  = threadIdx.x;
    const int warp = tid >> 5;
    const int lane = tid & 31;
    const int tau  = tid & 63;
    const int s    = tid >> 6;           // k-slice 0..3
    const int gb   = tau * 3;            // first owned gate
    const int k0   = s * 16;
    const int b0   = blockIdx.x * 8;

    // W slice into registers: w[g'][kp'] = (W[gb+g'][k0+2kp'], W[gb+g'][k0+2kp'+1])
    ull w[3][8];
#pragma unroll
    for (int g = 0; g < 3; g++)
#pragma unroll
        for (int kp = 0; kp < 8; kp++)
            w[g][kp] = *(const ull*)(Whh + (size_t)(gb + g) * HHH + k0 + 2 * kp);

    for (int e = tid; e < 512; e += 256) hsh[e] = 0.0f;

    // update-role constants (warp = row, lane = j and j+32)
    const int ur = warp;
    const int uj = lane;
    const float bR0 = __ldg(bhh + uj),        bR1 = __ldg(bhh + 32 + uj);
    const float bZ0 = __ldg(bhh + 64 + uj),   bZ1 = __ldg(bhh + 96 + uj);
    const float bN0 = __ldg(bhh + 128 + uj),  bN1 = __ldg(bhh + 160 + uj);

    const float* gxb = g_gx + (size_t)(b0 + ur) * G3;   // advance BB*G3 per t
    float* outb = g_out + (size_t)(b0 + ur) * HHH;

    float h0 = 0.0f, h1 = 0.0f;

    // prefetch gx for t=0
    float xr0 = __ldg(gxb + uj),       xr1 = __ldg(gxb + 32 + uj);
    float xz0 = __ldg(gxb + 64 + uj),  xz1 = __ldg(gxb + 96 + uj);
    float xn0 = __ldg(gxb + 128 + uj), xn1 = __ldg(gxb + 160 + uj);

    __syncthreads();

#pragma unroll 1
    for (int t = 0; t < TT; ++t) {
        // ---- dot phase: all 8 rows against register-resident W slice ----
        ull acc[3][8];
#pragma unroll
        for (int g = 0; g < 3; g++)
#pragma unroll
            for (int r = 0; r < 8; r++) acc[g][r] = 0ULL;

#pragma unroll
        for (int r = 0; r < 8; r++) {
            const ulonglong2* hq = (const ulonglong2*)(hsh + r * 64 + k0);
            ulonglong2 u0 = hq[0], u1 = hq[1], u2 = hq[2], u3 = hq[3];  // broadcast
            ull h2[8] = {u0.x, u0.y, u1.x, u1.y, u2.x, u2.y, u3.x, u3.y};
#pragma unroll
            for (int kp = 0; kp < 8; kp++) {
                acc[0][r] = fma2(w[0][kp], h2[kp], acc[0][r]);
                acc[1][r] = fma2(w[1][kp], h2[kp], acc[1][r]);
                acc[2][r] = fma2(w[2][kp], h2[kp], acc[2][r]);
            }
        }
        {
            float* pb = psh + (size_t)s * (8 * G3);
#pragma unroll
            for (int r = 0; r < 8; r++) {
                float* pr = pb + r * G3 + gb;
                pr[0] = hsum2(acc[0][r]);
                pr[1] = hsum2(acc[1][r]);
                pr[2] = hsum2(acc[2][r]);
            }
        }
        __syncthreads();

        // ---- update phase ----
        float cr0 = xr0, cr1 = xr1, cz0 = xz0, cz1 = xz1, cn0 = xn0, cn1 = xn1;
        {   // prefetch next-t gx (latency hidden by next dot phase)
            const float* gn = gxb + (size_t)((t + 1 < TT) ? t + 1 : t) * (BB * G3);
            xr0 = __ldg(gn + uj);       xr1 = __ldg(gn + 32 + uj);
            xz0 = __ldg(gn + 64 + uj);  xz1 = __ldg(gn + 96 + uj);
            xn0 = __ldg(gn + 128 + uj); xn1 = __ldg(gn + 160 + uj);
        }

        float pr0 = bR0, pr1 = bR1, pz0 = bZ0, pz1 = bZ1, pn0 = bN0, pn1 = bN1;
#pragma unroll
        for (int sl = 0; sl < 4; sl++) {
            const float* base = psh + (size_t)sl * (8 * G3) + ur * G3;
            pr0 += base[uj];        pr1 += base[32 + uj];
            pz0 += base[64 + uj];   pz1 += base[96 + uj];
            pn0 += base[128 + uj];  pn1 += base[160 + uj];
        }

        float r0 = fsigmoid(cr0 + pr0), r1 = fsigmoid(cr1 + pr1);
        float z0 = fsigmoid(cz0 + pz0), z1 = fsigmoid(cz1 + pz1);
        float n0 = ftanhf(fmaf(r0, pn0, cn0));
        float n1 = ftanhf(fmaf(r1, pn1, cn1));
        h0 = fmaf(z0, h0 - n0, n0);
        h1 = fmaf(z1, h1 - n1, n1);

        hsh[ur * 64 + uj]      = h0;
        hsh[ur * 64 + 32 + uj] = h1;
        float* ot = outb + (size_t)t * (BB * HHH);
        ot[uj]      = h0;
        ot[32 + uj] = h1;
        __syncthreads();
    }
}

// ---------------------------------------------------------------------------
// Head: y[b] = fc2_b + fc2_w . relu(fc1_w @ h_last[b] + fc1_b)
// ---------------------------------------------------------------------------
__global__ void __launch_bounds__(256) head_kernel(
    const float* __restrict__ fc1w, const float* __restrict__ fc1b,
    const float* __restrict__ fc2w, const float* __restrict__ fc2b,
    float* __restrict__ y)
{
    __shared__ float s1[32 * 64];
    __shared__ float sb1[32];
    __shared__ float sw2[32];
    const int tid = threadIdx.x;
    for (int e = tid; e < 2048; e += 256) s1[e] = fc1w[e];
    if (tid < 32) { sb1[tid] = fc1b[tid]; sw2[tid] = fc2w[tid]; }
    __syncthreads();

    const int b = blockIdx.x * 256 + tid;
    const float* hp = g_out + ((size_t)(TT - 1) * BB + b) * HHH;
    float hv[64];
#pragma unroll
    for (int q = 0; q < 16; q++) {
        float4 v = *(const float4*)(hp + q * 4);
        hv[q * 4] = v.x; hv[q * 4 + 1] = v.y; hv[q * 4 + 2] = v.z; hv[q * 4 + 3] = v.w;
    }
    float acc = __ldg(fc2b);
#pragma unroll
    for (int j = 0; j < 32; j++) {
        float sacc = sb1[j];
#pragma unroll
        for (int k = 0; k < 64; k++) sacc = fmaf(s1[j * 64 + k], hv[k], sacc);
        acc = fmaf(sw2[j], fmaxf(sacc, 0.0f), acc);
    }
    y[b] = acc;
}

// ---------------------------------------------------------------------------
extern "C" void kernel_launch(void* const* d_in, const int* in_sizes, int n_in,
                              void* d_out, int out_size)
{
    const float* x    = (const float*)d_in[0];
    const float* Wih0 = (const float*)d_in[1];
    const float* Whh0 = (const float*)d_in[2];
    const float* bih0 = (const float*)d_in[3];
    const float* bhh0 = (const float*)d_in[4];
    const float* Wih1 = (const float*)d_in[5];
    const float* Whh1 = (const float*)d_in[6];
    const float* bih1 = (const float*)d_in[7];
    const float* bhh1 = (const float*)d_in[8];
    const float* Wih2 = (const float*)d_in[9];
    const float* Whh2 = (const float*)d_in[10];
    const float* bih2 = (const float*)d_in[11];
    const float* bhh2 = (const float*)d_in[12];
    const float* fc1w = (const float*)d_in[13];
    const float* fc1b = (const float*)d_in[14];
    const float* fc2w = (const float*)d_in[15];
    const float* fc2b = (const float*)d_in[16];
    float* y = (float*)d_out;
    (void)in_sizes; (void)n_in; (void)out_size;

    const int gemm64_smem = (32 * 192 + 64 * 33) * 8;   // 66048
    const int gemm16_smem = (8 * 192 + 64 * 9) * 8;     // 16896

    cudaFuncSetAttribute((const void*)gx_gemm<64, 0>,
                         cudaFuncAttributeMaxDynamicSharedMemorySize, gemm64_smem);

    float* outp = nullptr;
    cudaGetSymbolAddress((void**)&outp, g_out);

    const dim3 gg(16, 512);

    // layer 0
    gx_gemm<16, 1><<<gg, 256, gemm16_smem>>>(x, Wih0, bih0);
    gru_rec<<<128, 256>>>(Whh0, bhh0);
    // layer 1
    gx_gemm<64, 0><<<gg, 256, gemm64_smem>>>(outp, Wih1, bih1);
    gru_rec<<<128, 256>>>(Whh1, bhh1);
    // layer 2
    gx_gemm<64, 0><<<gg, 256, gemm64_smem>>>(outp, Wih2, bih2);
    gru_rec<<<128, 256>>>(Whh2, bhh2);
    // head
    head_kernel<<<4, 256>>>(fc1w, fc1b, fc2w, fc2b, y);
}

// round 8
// speedup vs baseline: 1.2145x; 1.1288x over previous
#include <cuda_runtime.h>
#include <cstdint>

#define BB 1024
#define TT 512
#define G3  192
#define HHH 64

typedef unsigned long long ull;

// Scratch (device globals — allocation-free per harness rules)
__device__ float g_gx[(size_t)TT * BB * G3];    // [t][b][192]
__device__ float g_out[(size_t)TT * BB * HHH];  // [t][b][64]

// ---- f32x2 packed helpers ----
__device__ __forceinline__ ull pk2(float lo, float hi) {
    ull r; asm("mov.b64 %0, {%1, %2};" : "=l"(r) : "f"(lo), "f"(hi)); return r;
}
__device__ __forceinline__ void upk2(ull v, float& lo, float& hi) {
    asm("mov.b64 {%0, %1}, %2;" : "=f"(lo), "=f"(hi) : "l"(v));
}
__device__ __forceinline__ ull fma2(ull a, ull b, ull c) {
    ull d; asm("fma.rn.f32x2 %0, %1, %2, %3;" : "=l"(d) : "l"(a), "l"(b), "l"(c)); return d;
}
__device__ __forceinline__ float hsum2(ull v) {
    float lo, hi; upk2(v, lo, hi); return lo + hi;
}
__device__ __forceinline__ float fsigmoid(float x) {
    return __fdividef(1.0f, 1.0f + __expf(-x));
}
__device__ __forceinline__ float ftanhf(float x) {
    float e = __expf(2.0f * x);
    return 1.0f - __fdividef(2.0f, e + 1.0f);
}

// ---------------------------------------------------------------------------
// gx GEMM, f32x2, occupancy-tuned.
// Block tile: 128 rows x 48 gates, 256 threads.
//   lane (tid&31) -> 4 rows (lane*4..+3), warp (tid>>5, 8 warps) -> 6 gates.
// Shared: wsh [K2][50 pad] ull (gates of this block), ish [K2][130 pad] ull
//   TRANSPOSED inputs so dot loads are aligned LDS.128, conflict-free.
// Grid: (8 row-tiles, 4 gate-tiles, 512 t). ~46KB smem -> 3 blocks/SM.
// g_gx[t][b][g] = bias[g] + sum_k in[row][k] * W[g][k]
// ---------------------------------------------------------------------------
template <int K2, int LAYER0>
__global__ void __launch_bounds__(256) gx_gemm(
    const float* __restrict__ in,
    const float* __restrict__ W,
    const float* __restrict__ bias)
{
    extern __shared__ float smf[];
    ull* wsh = (ull*)smf;                 // [K2][50]
    ull* ish = wsh + (size_t)K2 * 50;     // [K2][130]

    const int t     = blockIdx.z;
    const int b0    = blockIdx.x * 128;
    const int gate0 = blockIdx.y * 48;
    const int tid   = threadIdx.x;

    // W fill: wsh[kp][g] = W[gate0+g][2kp..2kp+1]
    for (int e = tid; e < 48 * K2; e += 256) {
        int kp = e % K2, g = e / K2;
        wsh[kp * 50 + g] = ((const ull*)W)[(size_t)(gate0 + g) * K2 + kp];
    }
    // input fill (transposed): ish[kp][m] = in_row(b0+m)[2kp..2kp+1]
    if (LAYER0) {
        for (int e = tid; e < 128 * K2; e += 256) {
            int kp = e % K2, m = e / K2;
            ish[kp * 130 + m] =
                ((const ull*)in)[((size_t)(b0 + m) * TT + t) * K2 + kp];
        }
    } else {
        for (int e = tid; e < 128 * K2; e += 256) {
            int kp = e % K2, m = e / K2;
            ish[kp * 130 + m] =
                ((const ull*)in)[((size_t)t * BB + b0 + m) * K2 + kp];
        }
    }
    __syncthreads();

    const int lane = tid & 31;
    const int w    = tid >> 5;
    const int r0   = lane * 4;
    const int g0   = w * 6;

    ull acc[4][6];
#pragma unroll
    for (int q = 0; q < 4; q++)
#pragma unroll
        for (int j = 0; j < 6; j++) acc[q][j] = 0ULL;

#pragma unroll 4
    for (int kp = 0; kp < K2; ++kp) {
        const ulonglong2* ip = (const ulonglong2*)(ish + (size_t)kp * 130 + r0);
        ulonglong2 i01 = ip[0], i23 = ip[1];
        const ulonglong2* wp = (const ulonglong2*)(wsh + (size_t)kp * 50 + g0);
        ulonglong2 w01 = wp[0], w23 = wp[1], w45 = wp[2];   // broadcast
        ull iv[4] = {i01.x, i01.y, i23.x, i23.y};
        ull wv[6] = {w01.x, w01.y, w23.x, w23.y, w45.x, w45.y};
#pragma unroll
        for (int q = 0; q < 4; q++)
#pragma unroll
            for (int j = 0; j < 6; j++)
                acc[q][j] = fma2(wv[j], iv[q], acc[q][j]);
    }

    float bb[6];
#pragma unroll
    for (int j = 0; j < 6; j++) bb[j] = __ldg(bias + gate0 + g0 + j);

#pragma unroll
    for (int q = 0; q < 4; q++) {
        float* op = g_gx + ((size_t)t * BB + b0 + r0 + q) * G3 + gate0 + g0;
        float2 v;
        v.x = hsum2(acc[q][0]) + bb[0]; v.y = hsum2(acc[q][1]) + bb[1]; *(float2*)(op)     = v;
        v.x = hsum2(acc[q][2]) + bb[2]; v.y = hsum2(acc[q][3]) + bb[3]; *(float2*)(op + 2) = v;
        v.x = hsum2(acc[q][4]) + bb[4]; v.y = hsum2(acc[q][5]) + bb[5]; *(float2*)(op + 4) = v;
    }
}

// ---------------------------------------------------------------------------
// Recurrent GRU layer. 128 blocks x 512 threads (16 warps); block owns 8 rows.
// Dot: thread (tau = tid&63, slice s = tid>>6) owns gates {tau,64+tau,128+tau},
// k in [8s, 8s+8), W in registers; accumulates all 8 rows (2 passes of 4).
// Partials -> psh[s][row][192] (stride-1 STS). Update: warp w -> row w>>1,
// lane j = (w&1)*32+lane; one h element per thread; sums 8 slice partials.
// ---------------------------------------------------------------------------
__global__ void __launch_bounds__(512, 1) gru_rec(
    const float* __restrict__ Whh, const float* __restrict__ bhh)
{
    extern __shared__ float sm[];
    float* hsh = sm;          // [8 rows][64]
    float* psh = sm + 512;    // [8 slices][8 rows][192]

    const int tid = threadIdx.x;
    const int tau = tid & 63;
    const int s   = tid >> 6;
    const int k0  = s * 8;
    const int b0  = blockIdx.x * 8;

    // register W: gates tau, 64+tau, 128+tau; k slice [k0, k0+8)
    ull w[3][4];
#pragma unroll
    for (int g = 0; g < 3; g++)
#pragma unroll
        for (int kp = 0; kp < 4; kp++)
            w[g][kp] = *(const ull*)(Whh + (size_t)(g * 64 + tau) * HHH + k0 + 2 * kp);

    hsh[tid] = 0.0f;

    const int warp = tid >> 5, lane = tid & 31;
    const int ur = warp >> 1;
    const int uj = (warp & 1) * 32 + lane;
    const float bR = __ldg(bhh + uj);
    const float bZ = __ldg(bhh + 64 + uj);
    const float bN = __ldg(bhh + 128 + uj);

    const float* gxb = g_gx + (size_t)(b0 + ur) * G3;
    float* outb = g_out + (size_t)(b0 + ur) * HHH + uj;

    float* pwr = psh + (size_t)(s * 8) * G3 + tau;       // + r*192, cols +0/64/128
    const float* prd = psh + (size_t)ur * G3 + uj;       // + s*1536, cols +0/64/128

    float h = 0.0f;
    float xr = __ldg(gxb + uj), xz = __ldg(gxb + 64 + uj), xn = __ldg(gxb + 128 + uj);
    __syncthreads();

#pragma unroll 1
    for (int t = 0; t < TT; ++t) {
        // ---- dot phase: two passes of 4 rows ----
#pragma unroll
        for (int pp = 0; pp < 2; pp++) {
            ull a0[4], a1[4], a2[4];
#pragma unroll
            for (int r = 0; r < 4; r++) { a0[r] = 0; a1[r] = 0; a2[r] = 0; }
#pragma unroll
            for (int r = 0; r < 4; r++) {
                const ulonglong2* hq = (const ulonglong2*)(hsh + (pp * 4 + r) * 64 + k0);
                ulonglong2 u0 = hq[0], u1 = hq[1];   // 8 h values (broadcast)
                a0[r] = fma2(w[0][0], u0.x, a0[r]); a0[r] = fma2(w[0][1], u0.y, a0[r]);
                a0[r] = fma2(w[0][2], u1.x, a0[r]); a0[r] = fma2(w[0][3], u1.y, a0[r]);
                a1[r] = fma2(w[1][0], u0.x, a1[r]); a1[r] = fma2(w[1][1], u0.y, a1[r]);
                a1[r] = fma2(w[1][2], u1.x, a1[r]); a1[r] = fma2(w[1][3], u1.y, a1[r]);
                a2[r] = fma2(w[2][0], u0.x, a2[r]); a2[r] = fma2(w[2][1], u0.y, a2[r]);
                a2[r] = fma2(w[2][2], u1.x, a2[r]); a2[r] = fma2(w[2][3], u1.y, a2[r]);
            }
            float* pb = pwr + (size_t)(pp * 4) * G3;
#pragma unroll
            for (int r = 0; r < 4; r++) {
                pb[r * G3]       = hsum2(a0[r]);
                pb[r * G3 + 64]  = hsum2(a1[r]);
                pb[r * G3 + 128] = hsum2(a2[r]);
            }
        }
        __syncthreads();

        // ---- update phase: 1 element per thread ----
        float cr = xr, cz = xz, cn = xn;
        const float* gn = gxb + (size_t)((t + 1 < TT) ? t + 1 : t) * (BB * G3);
        xr = __ldg(gn + uj); xz = __ldg(gn + 64 + uj); xn = __ldg(gn + 128 + uj);

        float pr = bR, pz = bZ, pn = bN;
#pragma unroll
        for (int sl = 0; sl < 8; sl++) {
            const float* base = prd + (size_t)sl * (8 * G3);
            pr += base[0]; pz += base[64]; pn += base[128];
        }
        float r = fsigmoid(cr + pr);
        float z = fsigmoid(cz + pz);
        float n = ftanhf(fmaf(r, pn, cn));
        h = fmaf(z, h - n, n);

        hsh[ur * 64 + uj] = h;
        outb[(size_t)t * (BB * HHH)] = h;
        __syncthreads();
    }
}

// ---------------------------------------------------------------------------
// Head: y[b] = fc2_b + fc2_w . relu(fc1_w @ h_last[b] + fc1_b)
// ---------------------------------------------------------------------------
__global__ void __launch_bounds__(256) head_kernel(
    const float* __restrict__ fc1w, const float* __restrict__ fc1b,
    const float* __restrict__ fc2w, const float* __restrict__ fc2b,
    float* __restrict__ y)
{
    __shared__ float s1[32 * 64];
    __shared__ float sb1[32];
    __shared__ float sw2[32];
    const int tid = threadIdx.x;
    for (int e = tid; e < 2048; e += 256) s1[e] = fc1w[e];
    if (tid < 32) { sb1[tid] = fc1b[tid]; sw2[tid] = fc2w[tid]; }
    __syncthreads();

    const int b = blockIdx.x * 256 + tid;
    const float* hp = g_out + ((size_t)(TT - 1) * BB + b) * HHH;
    float hv[64];
#pragma unroll
    for (int q = 0; q < 16; q++) {
        float4 v = *(const float4*)(hp + q * 4);
        hv[q * 4] = v.x; hv[q * 4 + 1] = v.y; hv[q * 4 + 2] = v.z; hv[q * 4 + 3] = v.w;
    }
    float acc = __ldg(fc2b);
#pragma unroll
    for (int j = 0; j < 32; j++) {
        float sacc = sb1[j];
#pragma unroll
        for (int k = 0; k < 64; k++) sacc = fmaf(s1[j * 64 + k], hv[k], sacc);
        acc = fmaf(sw2[j], fmaxf(sacc, 0.0f), acc);
    }
    y[b] = acc;
}

// ---------------------------------------------------------------------------
extern "C" void kernel_launch(void* const* d_in, const int* in_sizes, int n_in,
                              void* d_out, int out_size)
{
    const float* x    = (const float*)d_in[0];
    const float* Wih0 = (const float*)d_in[1];
    const float* Whh0 = (const float*)d_in[2];
    const float* bih0 = (const float*)d_in[3];
    const float* bhh0 = (const float*)d_in[4];
    const float* Wih1 = (const float*)d_in[5];
    const float* Whh1 = (const float*)d_in[6];
    const float* bih1 = (const float*)d_in[7];
    const float* bhh1 = (const float*)d_in[8];
    const float* Wih2 = (const float*)d_in[9];
    const float* Whh2 = (const float*)d_in[10];
    const float* bih2 = (const float*)d_in[11];
    const float* bhh2 = (const float*)d_in[12];
    const float* fc1w = (const float*)d_in[13];
    const float* fc1b = (const float*)d_in[14];
    const float* fc2w = (const float*)d_in[15];
    const float* fc2b = (const float*)d_in[16];
    float* y = (float*)d_out;
    (void)in_sizes; (void)n_in; (void)out_size;

    const int gemm64_smem = (32 * 50 + 32 * 130) * 8;   // 46080
    const int gemm16_smem = (8 * 50 + 8 * 130) * 8;     // 11520
    const int rec_smem    = (512 + 8 * 8 * 192) * 4;    // 51200

    cudaFuncSetAttribute((const void*)gx_gemm<32, 0>,
                         cudaFuncAttributeMaxDynamicSharedMemorySize, gemm64_smem);
    cudaFuncSetAttribute((const void*)gru_rec,
                         cudaFuncAttributeMaxDynamicSharedMemorySize, rec_smem);

    float* outp = nullptr;
    cudaGetSymbolAddress((void**)&outp, g_out);

    const dim3 gg(8, 4, 512);   // row-tiles, gate-tiles, t

    // layer 0 (K=16)
    gx_gemm<8, 1><<<gg, 256, gemm16_smem>>>(x, Wih0, bih0);
    gru_rec<<<128, 512, rec_smem>>>(Whh0, bhh0);
    // layer 1 (K=64)
    gx_gemm<32, 0><<<gg, 256, gemm64_smem>>>(outp, Wih1, bih1);
    gru_rec<<<128, 512, rec_smem>>>(Whh1, bhh1);
    // layer 2 (K=64)
    gx_gemm<32, 0><<<gg, 256, gemm64_smem>>>(outp, Wih2, bih2);
    gru_rec<<<128, 512, rec_smem>>>(Whh2, bhh2);
    // head
    head_kernel<<<4, 256>>>(fc1w, fc1b, fc2w, fc2b, y);
}

// round 9
// speedup vs baseline: 1.5873x; 1.3069x over previous
#include <cuda_runtime.h>
#include <cstdint>

#define BB 1024
#define TT 512
#define G3  192
#define HHH 64

typedef unsigned long long ull;

// Scratch (device globals — allocation-free per harness rules)
__device__ float g_bufA[(size_t)TT * BB * HHH];  // layer0 outputs [t][b][64]
__device__ float g_bufB[(size_t)TT * BB * HHH];  // layer1 outputs [t][b][64]
__device__ float g_hlast[BB * HHH];              // layer2 h at t=T-1

// ---- f32x2 packed helpers ----
__device__ __forceinline__ void upk2(ull v, float& lo, float& hi) {
    asm("mov.b64 {%0, %1}, %2;" : "=f"(lo), "=f"(hi) : "l"(v));
}
__device__ __forceinline__ ull fma2(ull a, ull b, ull c) {
    ull d; asm("fma.rn.f32x2 %0, %1, %2, %3;" : "=l"(d) : "l"(a), "l"(b), "l"(c)); return d;
}
__device__ __forceinline__ float hsum2(ull v) {
    float lo, hi; upk2(v, lo, hi); return lo + hi;
}
__device__ __forceinline__ float fsigmoid(float x) {
    return __fdividef(1.0f, 1.0f + __expf(-x));
}
__device__ __forceinline__ float ftanhf(float x) {
    float e = __expf(2.0f * x);
    return 1.0f - __fdividef(2.0f, e + 1.0f);
}

// ---------------------------------------------------------------------------
// Fused GRU layer: input projection + recurrence in one kernel.
// 128 blocks x 512 threads; block owns batch rows [8*blk, 8*blk+8).
//
// Thread map: tau = (lane&3)|(warp<<2) in 0..63 (gate triple: tau,64+tau,128+tau),
//             s = (lane>>2)&7 (k-slice, 8 floats of both hidden-k and input-k).
// W_hh and W_ih slices live in REGISTERS. Per step:
//   dot:    acc 4 planes (r,z,nh,nx) x 8 rows over slice k's (2 passes of 4 rows),
//           hsum -> shfl_xor(4) pairwise slice reduce -> even-s threads store
//           float4(r,z,nh,nx) to psh[4 slice-pairs][8 rows][64 tau].
//   update: warp w -> row w>>1, lane j -> h element; sum 4 psh quads,
//           apply GRU gates, write h to shared + out to gmem; stage next x.
// INW = 16 (layer0 reads x [b][t][16]) or 64 (reads prev layer [t][b][64]).
// WALL = 1: write all timesteps; 0: write only t=T-1 (to g_hlast).
// ---------------------------------------------------------------------------
template <int INW, int WALL>
__global__ void __launch_bounds__(512, 1) gru_fused(
    const float* __restrict__ xin,
    const float* __restrict__ Wih, const float* __restrict__ Whh,
    const float* __restrict__ bih, const float* __restrict__ bhh,
    float* __restrict__ outbuf)
{
    extern __shared__ float sm[];
    float* hsh = sm;                                   // [8][64]
    float* xsh = sm + 512;                             // [2][8][INW]
    float4* psh4 = (float4*)(sm + 512 + 2 * 8 * INW);  // [4][8][64]

    const int tid  = threadIdx.x;
    const int warp = tid >> 5;
    const int lane = tid & 31;
    const int tau  = (lane & 3) | (warp << 2);   // 0..63
    const int s    = (lane >> 2) & 7;            // 0..7
    const int k0   = 8 * s;
    const int b0   = blockIdx.x * 8;

    // --- W slices into registers ---
    ull wh[3][4];
#pragma unroll
    for (int g = 0; g < 3; g++)
#pragma unroll
        for (int kp = 0; kp < 4; kp++)
            wh[g][kp] = *(const ull*)(Whh + (size_t)(g * 64 + tau) * HHH + k0 + 2 * kp);

    constexpr int NXU = (INW == 64) ? 4 : 1;
    ull wx[3][NXU];
    if (INW == 64) {
#pragma unroll
        for (int g = 0; g < 3; g++)
#pragma unroll
            for (int kp = 0; kp < NXU; kp++)
                wx[g][kp] = *(const ull*)(Wih + (size_t)(g * 64 + tau) * 64 + k0 + 2 * kp);
    } else {
#pragma unroll
        for (int g = 0; g < 3; g++)
            wx[g][0] = *(const ull*)(Wih + (size_t)(g * 64 + tau) * 16 + 2 * s);
    }

    // --- update-role constants ---
    const int ur = warp >> 1;                 // row 0..7
    const int uj = (warp & 1) * 32 + lane;    // h element 0..63
    const float bR  = __ldg(bih + uj)      + __ldg(bhh + uj);
    const float bZ  = __ldg(bih + 64 + uj) + __ldg(bhh + 64 + uj);
    const float bNx = __ldg(bih + 128 + uj);
    const float bNh = __ldg(bhh + 128 + uj);

    float* outp = WALL ? (outbuf + (size_t)(b0 + ur) * HHH + uj)
                       : (outbuf + (size_t)(b0 + ur) * HHH + uj);

    // --- init: zero h, stage x for t=0 ---
    hsh[tid < 512 ? tid : 0] = 0.0f;
    if (INW == 64) {
        int row = tid >> 6, kk = tid & 63;
        xsh[row * 64 + kk] = __ldg(xin + ((size_t)0 * BB + b0 + row) * 64 + kk);
    } else {
        if (tid < 128) {
            int row = tid >> 4, kk = tid & 15;
            xsh[row * 16 + kk] = __ldg(xin + ((size_t)(b0 + row) * TT + 0) * 16 + kk);
        }
    }
    float h = 0.0f;
    __syncthreads();

#pragma unroll 1
    for (int t = 0; t < TT; ++t) {
        const float* xb = xsh + (t & 1) * (8 * INW);

        // ---- dot phase: 2 passes of 4 rows ----
#pragma unroll
        for (int p = 0; p < 2; p++) {
            ull aR[4], aZ[4], aNh[4], aNx[4];
#pragma unroll
            for (int r = 0; r < 4; r++) { aR[r] = 0; aZ[r] = 0; aNh[r] = 0; aNx[r] = 0; }
#pragma unroll
            for (int r = 0; r < 4; r++) {
                const int row = p * 4 + r;
                const ulonglong2* hq = (const ulonglong2*)(hsh + row * 64 + k0);
                ulonglong2 u0 = hq[0], u1 = hq[1];
                aR[r]  = fma2(wh[0][0], u0.x, aR[r]);  aR[r]  = fma2(wh[0][1], u0.y, aR[r]);
                aR[r]  = fma2(wh[0][2], u1.x, aR[r]);  aR[r]  = fma2(wh[0][3], u1.y, aR[r]);
                aZ[r]  = fma2(wh[1][0], u0.x, aZ[r]);  aZ[r]  = fma2(wh[1][1], u0.y, aZ[r]);
                aZ[r]  = fma2(wh[1][2], u1.x, aZ[r]);  aZ[r]  = fma2(wh[1][3], u1.y, aZ[r]);
                aNh[r] = fma2(wh[2][0], u0.x, aNh[r]); aNh[r] = fma2(wh[2][1], u0.y, aNh[r]);
                aNh[r] = fma2(wh[2][2], u1.x, aNh[r]); aNh[r] = fma2(wh[2][3], u1.y, aNh[r]);
                if (INW == 64) {
                    const ulonglong2* xq = (const ulonglong2*)(xb + row * 64 + k0);
                    ulonglong2 v0 = xq[0], v1 = xq[1];
                    aR[r]  = fma2(wx[0][0], v0.x, aR[r]);  aR[r]  = fma2(wx[0][1], v0.y, aR[r]);
                    aR[r]  = fma2(wx[0][2], v1.x, aR[r]);  aR[r]  = fma2(wx[0][3], v1.y, aR[r]);
                    aZ[r]  = fma2(wx[1][0], v0.x, aZ[r]);  aZ[r]  = fma2(wx[1][1], v0.y, aZ[r]);
                    aZ[r]  = fma2(wx[1][2], v1.x, aZ[r]);  aZ[r]  = fma2(wx[1][3], v1.y, aZ[r]);
                    aNx[r] = fma2(wx[2][0], v0.x, aNx[r]); aNx[r] = fma2(wx[2][1], v0.y, aNx[r]);
                    aNx[r] = fma2(wx[2][2], v1.x, aNx[r]); aNx[r] = fma2(wx[2][3], v1.y, aNx[r]);
                } else {
                    ull xv = *(const ull*)(xb + row * 16 + 2 * s);
                    aR[r]  = fma2(wx[0][0], xv, aR[r]);
                    aZ[r]  = fma2(wx[1][0], xv, aZ[r]);
                    aNx[r] = fma2(wx[2][0], xv, aNx[r]);
                }
            }
            // slice-pair reduce + store
#pragma unroll
            for (int r = 0; r < 4; r++) {
                float fr  = hsum2(aR[r]);
                float fz  = hsum2(aZ[r]);
                float fnh = hsum2(aNh[r]);
                float fnx = hsum2(aNx[r]);
                fr  += __shfl_xor_sync(0xffffffffu, fr, 4);
                fz  += __shfl_xor_sync(0xffffffffu, fz, 4);
                fnh += __shfl_xor_sync(0xffffffffu, fnh, 4);
                fnx += __shfl_xor_sync(0xffffffffu, fnx, 4);
                if ((s & 1) == 0)
                    psh4[((s >> 1) * 8 + (p * 4 + r)) * 64 + tau] =
                        make_float4(fr, fz, fnh, fnx);
            }
        }
        __syncthreads();

        // ---- update phase ----
        float4 q0 = psh4[(0 * 8 + ur) * 64 + uj];
        float4 q1 = psh4[(1 * 8 + ur) * 64 + uj];
        float4 q2 = psh4[(2 * 8 + ur) * 64 + uj];
        float4 q3 = psh4[(3 * 8 + ur) * 64 + uj];
        float pr  = (q0.x + q1.x) + (q2.x + q3.x);
        float pz  = (q0.y + q1.y) + (q2.y + q3.y);
        float pnh = (q0.z + q1.z) + (q2.z + q3.z);
        float pnx = (q0.w + q1.w) + (q2.w + q3.w);

        float r = fsigmoid(pr + bR);
        float z = fsigmoid(pz + bZ);
        float n = ftanhf(pnx + bNx + r * (pnh + bNh));
        h = fmaf(z, h - n, n);

        hsh[ur * 64 + uj] = h;
        if (WALL) {
            outp[(size_t)t * (BB * HHH)] = h;
        } else if (t == TT - 1) {
            outp[0] = h;
        }

        // stage next timestep's input
        const int tn = (t + 1 < TT) ? t + 1 : t;
        float* xnb = xsh + ((t + 1) & 1) * (8 * INW);
        if (INW == 64) {
            int row = tid >> 6, kk = tid & 63;
            xnb[row * 64 + kk] = __ldg(xin + ((size_t)tn * BB + b0 + row) * 64 + kk);
        } else {
            if (tid < 128) {
                int row = tid >> 4, kk = tid & 15;
                xnb[row * 16 + kk] = __ldg(xin + ((size_t)(b0 + row) * TT + tn) * 16 + kk);
            }
        }
        __syncthreads();
    }
}

// ---------------------------------------------------------------------------
// Head: y[b] = fc2_b + fc2_w . relu(fc1_w @ h_last[b] + fc1_b)
// ---------------------------------------------------------------------------
__global__ void __launch_bounds__(256) head_kernel(
    const float* __restrict__ fc1w, const float* __restrict__ fc1b,
    const float* __restrict__ fc2w, const float* __restrict__ fc2b,
    float* __restrict__ y)
{
    __shared__ float s1[32 * 64];
    __shared__ float sb1[32];
    __shared__ float sw2[32];
    const int tid = threadIdx.x;
    for (int e = tid; e < 2048; e += 256) s1[e] = fc1w[e];
    if (tid < 32) { sb1[tid] = fc1b[tid]; sw2[tid] = fc2w[tid]; }
    __syncthreads();

    const int b = blockIdx.x * 256 + tid;
    const float* hp = g_hlast + (size_t)b * HHH;
    float hv[64];
#pragma unroll
    for (int q = 0; q < 16; q++) {
        float4 v = *(const float4*)(hp + q * 4);
        hv[q * 4] = v.x; hv[q * 4 + 1] = v.y; hv[q * 4 + 2] = v.z; hv[q * 4 + 3] = v.w;
    }
    float acc = __ldg(fc2b);
#pragma unroll
    for (int j = 0; j < 32; j++) {
        float sacc = sb1[j];
#pragma unroll
        for (int k = 0; k < 64; k++) sacc = fmaf(s1[j * 64 + k], hv[k], sacc);
        acc = fmaf(sw2[j], fmaxf(sacc, 0.0f), acc);
    }
    y[b] = acc;
}

// ---------------------------------------------------------------------------
extern "C" void kernel_launch(void* const* d_in, const int* in_sizes, int n_in,
                              void* d_out, int out_size)
{
    const float* x    = (const float*)d_in[0];
    const float* Wih0 = (const float*)d_in[1];
    const float* Whh0 = (const float*)d_in[2];
    const float* bih0 = (const float*)d_in[3];
    const float* bhh0 = (const float*)d_in[4];
    const float* Wih1 = (const float*)d_in[5];
    const float* Whh1 = (const float*)d_in[6];
    const float* bih1 = (const float*)d_in[7];
    const float* bhh1 = (const float*)d_in[8];
    const float* Wih2 = (const float*)d_in[9];
    const float* Whh2 = (const float*)d_in[10];
    const float* bih2 = (const float*)d_in[11];
    const float* bhh2 = (const float*)d_in[12];
    const float* fc1w = (const float*)d_in[13];
    const float* fc1b = (const float*)d_in[14];
    const float* fc2w = (const float*)d_in[15];
    const float* fc2b = (const float*)d_in[16];
    float* y = (float*)d_out;
    (void)in_sizes; (void)n_in; (void)out_size;

    float *bufA = nullptr, *bufB = nullptr, *hlast = nullptr;
    cudaGetSymbolAddress((void**)&bufA, g_bufA);
    cudaGetSymbolAddress((void**)&bufB, g_bufB);
    cudaGetSymbolAddress((void**)&hlast, g_hlast);

    // dyn smem: hsh 512 + xsh 2*8*INW + psh 4*8*64*4 floats
    const int smem16 = (512 + 2 * 8 * 16 + 8192) * 4;   // 35840
    const int smem64 = (512 + 2 * 8 * 64 + 8192) * 4;   // 38912

    gru_fused<16, 1><<<128, 512, smem16>>>(x,    Wih0, Whh0, bih0, bhh0, bufA);
    gru_fused<64, 1><<<128, 512, smem64>>>(bufA, Wih1, Whh1, bih1, bhh1, bufB);
    gru_fused<64, 0><<<128, 512, smem64>>>(bufB, Wih2, Whh2, bih2, bhh2, hlast);
    head_kernel<<<4, 256>>>(fc1w, fc1b, fc2w, fc2b, y);
}